// round 1
// baseline (speedup 1.0000x reference)
#include <cuda_runtime.h>
#include <cuda_bf16.h>
#include <math.h>

// Problem constants
#define BATCH   4096
#define INDIM   512
#define LATENT  512
#define NHEAD   8
#define DHEAD   64
#define KVBN    1032            // H*(2D+1) = 8*129
#define LN_EPS  1e-5f

// ---------------- scratch (device globals; no runtime alloc allowed) ----------------
__device__ float g_hcat[BATCH * 1024];   // [h_ln | z]  (ld = 1024)
__device__ float g_h2  [BATCH * LATENT];
__device__ float g_kvb [BATCH * KVBN];

// ---------------- generic fp32 SGEMM: C = A(MxK) * B(KxN) + bias ----------------
// BM=128 BN=128 BK=16, 256 threads, 8x8 per-thread tile.
// Assumes: M % 128 == 0, K % 16 == 0, N % 4 == 0, lda/ldb/ldc % 4 == 0 (true for our shapes).
#define BM 128
#define BN 128
#define BK 16
#define TM 8
#define TN 8

__global__ __launch_bounds__(256) void sgemm_bias(
    int M, int N, int K,
    const float* __restrict__ A, int lda,
    const float* __restrict__ B, int ldb,
    const float* __restrict__ bias,
    float* __restrict__ C, int ldc)
{
    __shared__ float As[BK][BM];      // A staged transposed: As[k][m]
    __shared__ float Bs[BK][BN];

    const int tid = threadIdx.x;
    const int block_row = blockIdx.y * BM;
    const int block_col = blockIdx.x * BN;

    const int tx = tid & 15;          // 16 col groups
    const int ty = tid >> 4;          // 16 row groups

    // A tile load mapping: 128 rows x 16 cols = 512 float4; 2 per thread
    const int a_row  = tid >> 2;      // 0..63 (+64)
    const int a_c4   = (tid & 3) * 4; // col within BK
    // B tile load mapping: 16 rows x 128 cols = 512 float4; 2 per thread
    const int b_row  = tid >> 5;      // 0..7 (+8)
    const int b_c    = (tid & 31) * 4;

    float acc[TM][TN];
    #pragma unroll
    for (int i = 0; i < TM; i++)
        #pragma unroll
        for (int j = 0; j < TN; j++) acc[i][j] = 0.f;

    for (int k0 = 0; k0 < K; k0 += BK) {
        #pragma unroll
        for (int i = 0; i < 2; i++) {
            int r = a_row + i * 64;
            float4 v = *(const float4*)(A + (size_t)(block_row + r) * lda + k0 + a_c4);
            As[a_c4 + 0][r] = v.x;
            As[a_c4 + 1][r] = v.y;
            As[a_c4 + 2][r] = v.z;
            As[a_c4 + 3][r] = v.w;
        }
        #pragma unroll
        for (int i = 0; i < 2; i++) {
            int r = b_row + i * 8;
            float4 v = make_float4(0.f, 0.f, 0.f, 0.f);
            if (block_col + b_c < N)
                v = *(const float4*)(B + (size_t)(k0 + r) * ldb + block_col + b_c);
            *(float4*)&Bs[r][b_c] = v;
        }
        __syncthreads();

        #pragma unroll
        for (int kk = 0; kk < BK; kk++) {
            float a_reg[TM], b_reg[TN];
            float4 a0 = *(const float4*)&As[kk][ty * TM];
            float4 a1 = *(const float4*)&As[kk][ty * TM + 4];
            a_reg[0]=a0.x; a_reg[1]=a0.y; a_reg[2]=a0.z; a_reg[3]=a0.w;
            a_reg[4]=a1.x; a_reg[5]=a1.y; a_reg[6]=a1.z; a_reg[7]=a1.w;
            float4 b0 = *(const float4*)&Bs[kk][tx * TN];
            float4 b1 = *(const float4*)&Bs[kk][tx * TN + 4];
            b_reg[0]=b0.x; b_reg[1]=b0.y; b_reg[2]=b0.z; b_reg[3]=b0.w;
            b_reg[4]=b1.x; b_reg[5]=b1.y; b_reg[6]=b1.z; b_reg[7]=b1.w;
            #pragma unroll
            for (int i = 0; i < TM; i++)
                #pragma unroll
                for (int j = 0; j < TN; j++)
                    acc[i][j] = fmaf(a_reg[i], b_reg[j], acc[i][j]);
        }
        __syncthreads();
    }

    #pragma unroll
    for (int i = 0; i < TM; i++) {
        int row = block_row + ty * TM + i;
        #pragma unroll
        for (int j = 0; j < TN; j += 4) {
            int col = block_col + tx * TN + j;
            if (col < N) {
                float4 v;
                v.x = acc[i][j + 0] + bias[col + 0];
                v.y = acc[i][j + 1] + bias[col + 1];
                v.z = acc[i][j + 2] + bias[col + 2];
                v.w = acc[i][j + 3] + bias[col + 3];
                *(float4*)(C + (size_t)row * ldc + col) = v;
            }
        }
    }
}

// ---------------- LayerNorm (512) in-place on g_hcat[:, :512] + copy z into [:, 512:1024] ----------------
__global__ __launch_bounds__(256) void ln_concat_kernel(
    const float* __restrict__ z,
    const float* __restrict__ gamma,
    const float* __restrict__ beta)
{
    const int b = blockIdx.x;
    float* row = g_hcat + (size_t)b * 1024;
    const float* zr = z + (size_t)b * LATENT;
    const int tid = threadIdx.x;

    float v0 = row[tid];
    float v1 = row[tid + 256];

    __shared__ float red[256];
    red[tid] = v0 + v1;
    __syncthreads();
    #pragma unroll
    for (int s = 128; s > 0; s >>= 1) {
        if (tid < s) red[tid] += red[tid + s];
        __syncthreads();
    }
    const float mu = red[0] * (1.f / 512.f);
    __syncthreads();

    float d0 = v0 - mu, d1 = v1 - mu;
    red[tid] = d0 * d0 + d1 * d1;
    __syncthreads();
    #pragma unroll
    for (int s = 128; s > 0; s >>= 1) {
        if (tid < s) red[tid] += red[tid + s];
        __syncthreads();
    }
    const float var = red[0] * (1.f / 512.f);
    const float inv = rsqrtf(var + LN_EPS);

    row[tid]       = d0 * inv * gamma[tid]       + beta[tid];
    row[tid + 256] = d1 * inv * gamma[tid + 256] + beta[tid + 256];
    // concat: z into second half
    row[512 + tid]       = zr[tid];
    row[512 + tid + 256] = zr[tid + 256];
}

// ---------------- Oja update: one block per (b,h); W tile staged in SMEM (single HBM read) ----------------
__global__ __launch_bounds__(256) void oja_final_kernel(
    const float* __restrict__ W,
    float* __restrict__ out)
{
    const int bh = blockIdx.x;              // b*H + h
    const int b  = bh >> 3;
    const int h  = bh & 7;

    const float4* __restrict__ W4 = (const float4*)(W   + (size_t)bh * (DHEAD * DHEAD));
    float4* __restrict__       O4 = (float4*)      (out + (size_t)bh * (DHEAD * DHEAD));
    const float* __restrict__ row = g_kvb + (size_t)b * KVBN + h * (2 * DHEAD + 1);

    __shared__ float4 sW[DHEAD * DHEAD / 4];   // 16 KB
    __shared__ float  s_vs[DHEAD];
    __shared__ float  s_ks[DHEAD];             // logits, then final ks
    __shared__ float  part[16][DHEAD];         // partial ks_remove per d-group
    __shared__ float  red[DHEAD];
    __shared__ float  s_lr, s_max, s_sum;

    const int tid = threadIdx.x;
    if (tid < DHEAD) {
        s_ks[tid] = row[tid];                      // k logits
        s_vs[tid] = tanhf(row[DHEAD + tid]);       // vs
    }
    if (tid == 0) s_lr = 1.f / (1.f + expf(-row[2 * DHEAD]));
    __syncthreads();

    const int c4 = tid & 15;     // float4 column (covers e = 4*c4 .. 4*c4+3)
    const int dg = tid >> 4;     // d-group 0..15

    float p0 = 0.f, p1 = 0.f, p2 = 0.f, p3 = 0.f;
    #pragma unroll
    for (int i = 0; i < 4; i++) {
        int d = dg + 16 * i;
        float4 w = W4[d * 16 + c4];
        sW[d * 16 + c4] = w;
        float v = s_vs[d];
        p0 = fmaf(w.x, v, p0);
        p1 = fmaf(w.y, v, p1);
        p2 = fmaf(w.z, v, p2);
        p3 = fmaf(w.w, v, p3);
    }
    part[dg][4 * c4 + 0] = p0;
    part[dg][4 * c4 + 1] = p1;
    part[dg][4 * c4 + 2] = p2;
    part[dg][4 * c4 + 3] = p3;
    __syncthreads();

    if (tid < DHEAD) {
        float rm = 0.f;
        #pragma unroll
        for (int g = 0; g < 16; g++) rm += part[g][tid];
        red[tid] = s_ks[tid] - rm;                 // softmax logits
    }
    __syncthreads();
    if (tid == 0) {
        float mx = red[0];
        #pragma unroll
        for (int e = 1; e < DHEAD; e++) mx = fmaxf(mx, red[e]);
        s_max = mx;
    }
    __syncthreads();
    if (tid < DHEAD) red[tid] = expf(red[tid] - s_max);
    __syncthreads();
    if (tid == 0) {
        float s = 0.f;
        #pragma unroll
        for (int e = 0; e < DHEAD; e++) s += red[e];
        s_sum = s;
    }
    __syncthreads();
    if (tid < DHEAD) s_ks[tid] = red[tid] * (s_lr / s_sum);
    __syncthreads();

    #pragma unroll
    for (int i = 0; i < 4; i++) {
        int d = dg + 16 * i;
        float4 w = sW[d * 16 + c4];
        float v = s_vs[d];
        float4 o;
        o.x = fmaf(v, s_ks[4 * c4 + 0], w.x);
        o.y = fmaf(v, s_ks[4 * c4 + 1], w.y);
        o.z = fmaf(v, s_ks[4 * c4 + 2], w.z);
        o.w = fmaf(v, s_ks[4 * c4 + 3], w.w);
        O4[d * 16 + c4] = o;
    }
}

// ---------------- launch ----------------
extern "C" void kernel_launch(void* const* d_in, const int* in_sizes, int n_in,
                              void* d_out, int out_size)
{
    const float* x     = (const float*)d_in[0];
    const float* z     = (const float*)d_in[1];
    const float* W     = (const float*)d_in[2];
    const float* ip_w  = (const float*)d_in[3];
    const float* ip_b  = (const float*)d_in[4];
    const float* ln_g  = (const float*)d_in[5];
    const float* ln_b  = (const float*)d_in[6];
    const float* mg_w  = (const float*)d_in[7];
    const float* mg_b  = (const float*)d_in[8];
    const float* kvb_w = (const float*)d_in[9];
    const float* kvb_b = (const float*)d_in[10];
    float* out = (float*)d_out;

    void *p_hcat, *p_h2, *p_kvb;
    cudaGetSymbolAddress(&p_hcat, g_hcat);
    cudaGetSymbolAddress(&p_h2,   g_h2);
    cudaGetSymbolAddress(&p_kvb,  g_kvb);
    float* hcat = (float*)p_hcat;
    float* h2   = (float*)p_h2;
    float* kvb  = (float*)p_kvb;

    // 1) h = x @ ip_w + ip_b  -> hcat[:, :512]
    {
        dim3 grid(LATENT / BN, BATCH / BM);
        sgemm_bias<<<grid, 256>>>(BATCH, LATENT, INDIM, x, INDIM, ip_w, LATENT, ip_b, hcat, 1024);
    }
    // 2) LayerNorm in place + copy z into hcat[:, 512:]
    ln_concat_kernel<<<BATCH, 256>>>(z, ln_g, ln_b);
    // 3) h2 = hcat @ mg_w + mg_b
    {
        dim3 grid(LATENT / BN, BATCH / BM);
        sgemm_bias<<<grid, 256>>>(BATCH, LATENT, 1024, hcat, 1024, mg_w, LATENT, mg_b, h2, LATENT);
    }
    // 4) kvb = h2 @ kvb_w + kvb_b
    {
        dim3 grid((KVBN + BN - 1) / BN, BATCH / BM);
        sgemm_bias<<<grid, 256>>>(BATCH, KVBN, LATENT, h2, LATENT, kvb_w, KVBN, kvb_b, kvb, KVBN);
    }
    // 5) Oja update fused: ks_remove, softmax, upd + W
    oja_final_kernel<<<BATCH * NHEAD, 256>>>(W, out);
}

// round 2
// speedup vs baseline: 1.3911x; 1.3911x over previous
#include <cuda_runtime.h>
#include <cuda_bf16.h>
#include <math.h>
#include <stdint.h>

// Problem constants
#define BATCH   4096
#define INDIM   512
#define LATENT  512
#define NHEAD   8
#define DHEAD   64
#define KVBN    1032            // H*(2D+1) = 8*129
#define LN_EPS  1e-5f

// ---------------- scratch (device globals; no runtime alloc allowed) ----------------
__device__ float g_hcat[BATCH * 1024];   // [h_ln | z]  (ld = 1024)
__device__ float g_h2  [BATCH * LATENT];
__device__ float g_kvb [BATCH * KVBN];

__device__ __forceinline__ float to_tf32(float x) {
    float y;
    asm("cvt.rna.tf32.f32 %0, %1;" : "=f"(y) : "f"(x));
    return y;
}

// ---------------- TF32 tensor-core GEMM: C = A(MxK) * B(KxN) + bias ----------------
// BM=128, BN=64, BK=32, 256 threads (8 warps), warp tile 32x32 via m16n8k8 tf32 mma.
// A staged k-major in SMEM (transposed), B staged k-row-major. Requires:
// M%128==0, K%32==0, lda/ldb 16B-aligned rows (true for all three GEMMs here).
#define GBM 128
#define GBN 64
#define GBK 32

template<bool NB>
__global__ __launch_bounds__(256) void tf32_gemm(
    int M, int N, int K,
    const float* __restrict__ A, int lda,
    const float* __restrict__ B, int ldb,
    const float* __restrict__ bias,
    float* __restrict__ C, int ldc)
{
    __shared__ float As[GBK][GBM + 4];   // [k][m], pad 4
    __shared__ float Bs[GBK][GBN + 4];   // [k][n], pad 4

    const int tid  = threadIdx.x;
    const int wid  = tid >> 5;
    const int lane = tid & 31;
    const int grp  = lane >> 2;     // 0..7
    const int tig  = lane & 3;      // 0..3
    const int warp_m = (wid & 3) * 32;   // 4 warps along M
    const int warp_n = (wid >> 2) * 32;  // 2 warps along N
    const int block_row = blockIdx.y * GBM;
    const int block_col = blockIdx.x * GBN;

    float acc[2][4][4];
    #pragma unroll
    for (int a = 0; a < 2; a++)
        #pragma unroll
        for (int b = 0; b < 4; b++)
            #pragma unroll
            for (int c = 0; c < 4; c++) acc[a][b][c] = 0.f;

    // Global->shared mappings
    const int a_row = tid >> 3;          // 0..31 (4 passes of 32 rows)
    const int a_col = (tid & 7) * 4;     // k within BK
    const int b_k   = tid >> 4;          // 0..15 (2 passes of 16 k-rows)
    const int b_col = (tid & 15) * 4;    // n within BN

    for (int k0 = 0; k0 < K; k0 += GBK) {
        // Stage A transposed: As[k][m]
        #pragma unroll
        for (int i = 0; i < 4; i++) {
            int r = a_row + 32 * i;
            float4 v = *(const float4*)(A + (size_t)(block_row + r) * lda + k0 + a_col);
            As[a_col + 0][r] = to_tf32(v.x);
            As[a_col + 1][r] = to_tf32(v.y);
            As[a_col + 2][r] = to_tf32(v.z);
            As[a_col + 3][r] = to_tf32(v.w);
        }
        // Stage B: Bs[k][n]
        #pragma unroll
        for (int i = 0; i < 2; i++) {
            int kk = b_k + 16 * i;
            float4 v = make_float4(0.f, 0.f, 0.f, 0.f);
            if (!NB || (block_col + b_col) < N)
                v = *(const float4*)(B + (size_t)(k0 + kk) * ldb + block_col + b_col);
            Bs[kk][b_col + 0] = to_tf32(v.x);
            Bs[kk][b_col + 1] = to_tf32(v.y);
            Bs[kk][b_col + 2] = to_tf32(v.z);
            Bs[kk][b_col + 3] = to_tf32(v.w);
        }
        __syncthreads();

        #pragma unroll
        for (int ks = 0; ks < 4; ks++) {
            const int k = ks * 8;
            uint32_t af[2][4], bf[4][2];
            #pragma unroll
            for (int mt = 0; mt < 2; mt++) {
                int m0 = warp_m + mt * 16;
                af[mt][0] = __float_as_uint(As[k + tig    ][m0 + grp]);
                af[mt][1] = __float_as_uint(As[k + tig    ][m0 + grp + 8]);
                af[mt][2] = __float_as_uint(As[k + tig + 4][m0 + grp]);
                af[mt][3] = __float_as_uint(As[k + tig + 4][m0 + grp + 8]);
            }
            #pragma unroll
            for (int nt = 0; nt < 4; nt++) {
                int n0 = warp_n + nt * 8;
                bf[nt][0] = __float_as_uint(Bs[k + tig    ][n0 + grp]);
                bf[nt][1] = __float_as_uint(Bs[k + tig + 4][n0 + grp]);
            }
            #pragma unroll
            for (int mt = 0; mt < 2; mt++)
                #pragma unroll
                for (int nt = 0; nt < 4; nt++) {
                    asm volatile(
                        "mma.sync.aligned.m16n8k8.row.col.f32.tf32.tf32.f32 "
                        "{%0,%1,%2,%3}, {%4,%5,%6,%7}, {%8,%9}, {%0,%1,%2,%3};\n"
                        : "+f"(acc[mt][nt][0]), "+f"(acc[mt][nt][1]),
                          "+f"(acc[mt][nt][2]), "+f"(acc[mt][nt][3])
                        : "r"(af[mt][0]), "r"(af[mt][1]), "r"(af[mt][2]), "r"(af[mt][3]),
                          "r"(bf[nt][0]), "r"(bf[nt][1]));
                }
        }
        __syncthreads();
    }

    // Epilogue: bias add + store (float2 pairs: c0/c1 and c2/c3 are adjacent cols)
    #pragma unroll
    for (int mt = 0; mt < 2; mt++) {
        int r0 = block_row + warp_m + mt * 16 + grp;
        #pragma unroll
        for (int nt = 0; nt < 4; nt++) {
            int c = block_col + warp_n + nt * 8 + tig * 2;
            if (!NB || c < N) {
                float b0 = bias[c], b1 = bias[c + 1];
                float2 v0 = make_float2(acc[mt][nt][0] + b0, acc[mt][nt][1] + b1);
                *(float2*)(C + (size_t)r0 * ldc + c) = v0;
                float2 v1 = make_float2(acc[mt][nt][2] + b0, acc[mt][nt][3] + b1);
                *(float2*)(C + (size_t)(r0 + 8) * ldc + c) = v1;
            }
        }
    }
}

// ---------------- LayerNorm (512) in-place on g_hcat[:, :512] + copy z into [:, 512:1024] ----------------
__global__ __launch_bounds__(256) void ln_concat_kernel(
    const float* __restrict__ z,
    const float* __restrict__ gamma,
    const float* __restrict__ beta)
{
    const int b = blockIdx.x;
    float* row = g_hcat + (size_t)b * 1024;
    const float* zr = z + (size_t)b * LATENT;
    const int tid = threadIdx.x;

    float v0 = row[tid];
    float v1 = row[tid + 256];

    __shared__ float red[256];
    red[tid] = v0 + v1;
    __syncthreads();
    #pragma unroll
    for (int s = 128; s > 0; s >>= 1) {
        if (tid < s) red[tid] += red[tid + s];
        __syncthreads();
    }
    const float mu = red[0] * (1.f / 512.f);
    __syncthreads();

    float d0 = v0 - mu, d1 = v1 - mu;
    red[tid] = d0 * d0 + d1 * d1;
    __syncthreads();
    #pragma unroll
    for (int s = 128; s > 0; s >>= 1) {
        if (tid < s) red[tid] += red[tid + s];
        __syncthreads();
    }
    const float var = red[0] * (1.f / 512.f);
    const float inv = rsqrtf(var + LN_EPS);

    row[tid]       = d0 * inv * gamma[tid]       + beta[tid];
    row[tid + 256] = d1 * inv * gamma[tid + 256] + beta[tid + 256];
    row[512 + tid]       = zr[tid];
    row[512 + tid + 256] = zr[tid + 256];
}

// ---------------- Oja update: one block per (b,h); W tile staged in SMEM (single HBM read) ----------------
__global__ __launch_bounds__(256) void oja_final_kernel(
    const float* __restrict__ W,
    float* __restrict__ out)
{
    const int bh = blockIdx.x;              // b*H + h
    const int b  = bh >> 3;
    const int h  = bh & 7;

    const float4* __restrict__ W4 = (const float4*)(W   + (size_t)bh * (DHEAD * DHEAD));
    float4* __restrict__       O4 = (float4*)      (out + (size_t)bh * (DHEAD * DHEAD));
    const float* __restrict__ row = g_kvb + (size_t)b * KVBN + h * (2 * DHEAD + 1);

    __shared__ float4 sW[DHEAD * DHEAD / 4];   // 16 KB
    __shared__ float  s_vs[DHEAD];
    __shared__ float  s_ks[DHEAD];
    __shared__ float  part[16][DHEAD];
    __shared__ float  red[DHEAD];
    __shared__ float  s_lr, s_max, s_sum;

    const int tid = threadIdx.x;
    if (tid < DHEAD) {
        s_ks[tid] = row[tid];
        s_vs[tid] = tanhf(row[DHEAD + tid]);
    }
    if (tid == 0) s_lr = 1.f / (1.f + expf(-row[2 * DHEAD]));
    __syncthreads();

    const int c4 = tid & 15;
    const int dg = tid >> 4;

    float p0 = 0.f, p1 = 0.f, p2 = 0.f, p3 = 0.f;
    #pragma unroll
    for (int i = 0; i < 4; i++) {
        int d = dg + 16 * i;
        float4 w = W4[d * 16 + c4];
        sW[d * 16 + c4] = w;
        float v = s_vs[d];
        p0 = fmaf(w.x, v, p0);
        p1 = fmaf(w.y, v, p1);
        p2 = fmaf(w.z, v, p2);
        p3 = fmaf(w.w, v, p3);
    }
    part[dg][4 * c4 + 0] = p0;
    part[dg][4 * c4 + 1] = p1;
    part[dg][4 * c4 + 2] = p2;
    part[dg][4 * c4 + 3] = p3;
    __syncthreads();

    if (tid < DHEAD) {
        float rm = 0.f;
        #pragma unroll
        for (int g = 0; g < 16; g++) rm += part[g][tid];
        red[tid] = s_ks[tid] - rm;
    }
    __syncthreads();
    if (tid == 0) {
        float mx = red[0];
        #pragma unroll
        for (int e = 1; e < DHEAD; e++) mx = fmaxf(mx, red[e]);
        s_max = mx;
    }
    __syncthreads();
    if (tid < DHEAD) red[tid] = expf(red[tid] - s_max);
    __syncthreads();
    if (tid == 0) {
        float s = 0.f;
        #pragma unroll
        for (int e = 0; e < DHEAD; e++) s += red[e];
        s_sum = s;
    }
    __syncthreads();
    if (tid < DHEAD) s_ks[tid] = red[tid] * (s_lr / s_sum);
    __syncthreads();

    #pragma unroll
    for (int i = 0; i < 4; i++) {
        int d = dg + 16 * i;
        float4 w = sW[d * 16 + c4];
        float v = s_vs[d];
        float4 o;
        o.x = fmaf(v, s_ks[4 * c4 + 0], w.x);
        o.y = fmaf(v, s_ks[4 * c4 + 1], w.y);
        o.z = fmaf(v, s_ks[4 * c4 + 2], w.z);
        o.w = fmaf(v, s_ks[4 * c4 + 3], w.w);
        O4[d * 16 + c4] = o;
    }
}

// ---------------- launch ----------------
extern "C" void kernel_launch(void* const* d_in, const int* in_sizes, int n_in,
                              void* d_out, int out_size)
{
    const float* x     = (const float*)d_in[0];
    const float* z     = (const float*)d_in[1];
    const float* W     = (const float*)d_in[2];
    const float* ip_w  = (const float*)d_in[3];
    const float* ip_b  = (const float*)d_in[4];
    const float* ln_g  = (const float*)d_in[5];
    const float* ln_b  = (const float*)d_in[6];
    const float* mg_w  = (const float*)d_in[7];
    const float* mg_b  = (const float*)d_in[8];
    const float* kvb_w = (const float*)d_in[9];
    const float* kvb_b = (const float*)d_in[10];
    float* out = (float*)d_out;

    void *p_hcat, *p_h2, *p_kvb;
    cudaGetSymbolAddress(&p_hcat, g_hcat);
    cudaGetSymbolAddress(&p_h2,   g_h2);
    cudaGetSymbolAddress(&p_kvb,  g_kvb);
    float* hcat = (float*)p_hcat;
    float* h2   = (float*)p_h2;
    float* kvb  = (float*)p_kvb;

    // 1) h = x @ ip_w + ip_b  -> hcat[:, :512]
    {
        dim3 grid(LATENT / GBN, BATCH / GBM);
        tf32_gemm<false><<<grid, 256>>>(BATCH, LATENT, INDIM, x, INDIM, ip_w, LATENT, ip_b, hcat, 1024);
    }
    // 2) LayerNorm in place + copy z into hcat[:, 512:]
    ln_concat_kernel<<<BATCH, 256>>>(z, ln_g, ln_b);
    // 3) h2 = hcat @ mg_w + mg_b
    {
        dim3 grid(LATENT / GBN, BATCH / GBM);
        tf32_gemm<false><<<grid, 256>>>(BATCH, LATENT, 1024, hcat, 1024, mg_w, LATENT, mg_b, h2, LATENT);
    }
    // 4) kvb = h2 @ kvb_w + kvb_b   (N=1032, needs bounds)
    {
        dim3 grid((KVBN + GBN - 1) / GBN, BATCH / GBM);
        tf32_gemm<true><<<grid, 256>>>(BATCH, KVBN, LATENT, h2, LATENT, kvb_w, KVBN, kvb_b, kvb, KVBN);
    }
    // 5) Oja update fused
    oja_final_kernel<<<BATCH * NHEAD, 256>>>(W, out);
}

// round 3
// speedup vs baseline: 1.6620x; 1.1947x over previous
#include <cuda_runtime.h>
#include <cuda_bf16.h>
#include <math.h>
#include <stdint.h>

// Problem constants
#define BATCH   4096
#define INDIM   512
#define LATENT  512
#define NHEAD   8
#define DHEAD   64
#define KVBN    1032            // H*(2D+1) = 8*129
#define LN_EPS  1e-5f

// ---------------- scratch (device globals; no runtime alloc allowed) ----------------
__device__ float g_hcat[BATCH * 1024];   // [h_ln | z]  (ld = 1024)
__device__ float g_h2  [BATCH * LATENT];
__device__ float g_kvb [BATCH * KVBN];

__device__ __forceinline__ float to_tf32(float x) {
    float y;
    asm("cvt.rna.tf32.f32 %0, %1;" : "=f"(y) : "f"(x));
    return y;
}

__device__ __forceinline__ uint32_t smem_u32(const void* p) {
    return (uint32_t)__cvta_generic_to_shared(p);
}
__device__ __forceinline__ void cp_async16(uint32_t dst, const void* src) {
    asm volatile("cp.async.cg.shared.global [%0], [%1], 16;\n" :: "r"(dst), "l"(src));
}
__device__ __forceinline__ void cp_commit() {
    asm volatile("cp.async.commit_group;\n");
}
__device__ __forceinline__ void cp_wait0() {
    asm volatile("cp.async.wait_group 0;\n");
}
__device__ __forceinline__ void cp_wait1() {
    asm volatile("cp.async.wait_group 1;\n");
}

// ---------------- TF32 tensor-core GEMM: C = A(MxK) * B(KxN) + bias ----------------
// BM=128, BN=128, BK=16, 128 threads (4 warps, 2x2), warp tile 64x64.
// cp.async double-buffered. As stored [m][k] (pad->stride 20), Bs [k][n] (pad->stride 136).
// Both layouts verified conflict-free for the mma fragment LDS patterns.
// Requires: M%128==0, K%16==0, N%4==0, 16B-aligned rows (true for all three GEMMs).
#define GBM 128
#define GBN 128
#define GBK 16
#define SA  20     // As row stride (floats)
#define SB  136    // Bs row stride (floats)

template<bool NB>
__global__ __launch_bounds__(128) void tf32_gemm(
    int M, int N, int K,
    const float* __restrict__ A, int lda,
    const float* __restrict__ B, int ldb,
    const float* __restrict__ bias,
    float* __restrict__ C, int ldc)
{
    __shared__ float As[2][GBM][SA];   // [buf][m][k]
    __shared__ float Bs[2][GBK][SB];   // [buf][k][n]

    const int tid  = threadIdx.x;
    const int wid  = tid >> 5;
    const int lane = tid & 31;
    const int grp  = lane >> 2;     // 0..7
    const int tig  = lane & 3;      // 0..3
    const int warp_m = (wid & 1) * 64;
    const int warp_n = (wid >> 1) * 64;
    const int block_row = blockIdx.y * GBM;
    const int block_col = blockIdx.x * GBN;

    float acc[4][8][4];
    #pragma unroll
    for (int a = 0; a < 4; a++)
        #pragma unroll
        for (int b = 0; b < 8; b++)
            #pragma unroll
            for (int c = 0; c < 4; c++) acc[a][b][c] = 0.f;

    // A tile: 128 rows x 16 k = 4 float4 per row; thread -> row tid, chunks 0..3
    const float* a_src_base = A + (size_t)(block_row + tid) * lda;
    // B tile: 16 k-rows x 128 n = 512 float4; thread i handles idx = tid + 128*i
    const int KT = K / GBK;

    auto load_tiles = [&](int buf, int kt) {
        const int k0 = kt * GBK;
        #pragma unroll
        for (int j = 0; j < 4; j++) {
            cp_async16(smem_u32(&As[buf][tid][j * 4]), a_src_base + k0 + j * 4);
        }
        #pragma unroll
        for (int i = 0; i < 4; i++) {
            int idx = tid + 128 * i;
            int kk  = idx >> 5;
            int c4  = (idx & 31) * 4;
            if (!NB || (block_col + c4) < N) {
                cp_async16(smem_u32(&Bs[buf][kk][c4]),
                           B + (size_t)(k0 + kk) * ldb + block_col + c4);
            }
        }
    };

    load_tiles(0, 0);
    cp_commit();

    for (int kt = 0; kt < KT; kt++) {
        const int buf = kt & 1;
        if (kt + 1 < KT) {
            load_tiles(buf ^ 1, kt + 1);
            cp_commit();
            cp_wait1();
        } else {
            cp_wait0();
        }
        __syncthreads();

        #pragma unroll
        for (int ks = 0; ks < 2; ks++) {
            const int k = ks * 8;
            uint32_t af[4][4], bf[8][2];
            #pragma unroll
            for (int mt = 0; mt < 4; mt++) {
                int m0 = warp_m + mt * 16;
                af[mt][0] = __float_as_uint(to_tf32(As[buf][m0 + grp    ][k + tig]));
                af[mt][1] = __float_as_uint(to_tf32(As[buf][m0 + grp + 8][k + tig]));
                af[mt][2] = __float_as_uint(to_tf32(As[buf][m0 + grp    ][k + tig + 4]));
                af[mt][3] = __float_as_uint(to_tf32(As[buf][m0 + grp + 8][k + tig + 4]));
            }
            #pragma unroll
            for (int nt = 0; nt < 8; nt++) {
                int n0 = warp_n + nt * 8;
                bf[nt][0] = __float_as_uint(to_tf32(Bs[buf][k + tig    ][n0 + grp]));
                bf[nt][1] = __float_as_uint(to_tf32(Bs[buf][k + tig + 4][n0 + grp]));
            }
            #pragma unroll
            for (int mt = 0; mt < 4; mt++)
                #pragma unroll
                for (int nt = 0; nt < 8; nt++) {
                    asm volatile(
                        "mma.sync.aligned.m16n8k8.row.col.f32.tf32.tf32.f32 "
                        "{%0,%1,%2,%3}, {%4,%5,%6,%7}, {%8,%9}, {%0,%1,%2,%3};\n"
                        : "+f"(acc[mt][nt][0]), "+f"(acc[mt][nt][1]),
                          "+f"(acc[mt][nt][2]), "+f"(acc[mt][nt][3])
                        : "r"(af[mt][0]), "r"(af[mt][1]), "r"(af[mt][2]), "r"(af[mt][3]),
                          "r"(bf[nt][0]), "r"(bf[nt][1]));
                }
        }
        __syncthreads();
    }

    // Epilogue: bias add + float2 stores
    #pragma unroll
    for (int mt = 0; mt < 4; mt++) {
        int r0 = block_row + warp_m + mt * 16 + grp;
        #pragma unroll
        for (int nt = 0; nt < 8; nt++) {
            int c = block_col + warp_n + nt * 8 + tig * 2;
            if (!NB || c < N) {
                float b0 = bias[c], b1 = bias[c + 1];
                float2 v0 = make_float2(acc[mt][nt][0] + b0, acc[mt][nt][1] + b1);
                *(float2*)(C + (size_t)r0 * ldc + c) = v0;
                float2 v1 = make_float2(acc[mt][nt][2] + b0, acc[mt][nt][3] + b1);
                *(float2*)(C + (size_t)(r0 + 8) * ldc + c) = v1;
            }
        }
    }
}

// ---------------- LayerNorm (512) in-place on g_hcat[:, :512] + copy z into [:, 512:1024] ----------------
__global__ __launch_bounds__(256) void ln_concat_kernel(
    const float* __restrict__ z,
    const float* __restrict__ gamma,
    const float* __restrict__ beta)
{
    const int b = blockIdx.x;
    float* row = g_hcat + (size_t)b * 1024;
    const float* zr = z + (size_t)b * LATENT;
    const int tid = threadIdx.x;

    float v0 = row[tid];
    float v1 = row[tid + 256];

    __shared__ float red[256];
    red[tid] = v0 + v1;
    __syncthreads();
    #pragma unroll
    for (int s = 128; s > 0; s >>= 1) {
        if (tid < s) red[tid] += red[tid + s];
        __syncthreads();
    }
    const float mu = red[0] * (1.f / 512.f);
    __syncthreads();

    float d0 = v0 - mu, d1 = v1 - mu;
    red[tid] = d0 * d0 + d1 * d1;
    __syncthreads();
    #pragma unroll
    for (int s = 128; s > 0; s >>= 1) {
        if (tid < s) red[tid] += red[tid + s];
        __syncthreads();
    }
    const float var = red[0] * (1.f / 512.f);
    const float inv = rsqrtf(var + LN_EPS);

    row[tid]       = d0 * inv * gamma[tid]       + beta[tid];
    row[tid + 256] = d1 * inv * gamma[tid + 256] + beta[tid + 256];
    row[512 + tid]       = zr[tid];
    row[512 + tid + 256] = zr[tid + 256];
}

// ---------------- Oja update: one block per (b,h); W tile staged in SMEM (single HBM read) ----------------
__global__ __launch_bounds__(256) void oja_final_kernel(
    const float* __restrict__ W,
    float* __restrict__ out)
{
    const int bh = blockIdx.x;              // b*H + h
    const int b  = bh >> 3;
    const int h  = bh & 7;

    const float4* __restrict__ W4 = (const float4*)(W   + (size_t)bh * (DHEAD * DHEAD));
    float4* __restrict__       O4 = (float4*)      (out + (size_t)bh * (DHEAD * DHEAD));
    const float* __restrict__ row = g_kvb + (size_t)b * KVBN + h * (2 * DHEAD + 1);

    __shared__ float4 sW[DHEAD * DHEAD / 4];   // 16 KB
    __shared__ float  s_vs[DHEAD];
    __shared__ float  s_ks[DHEAD];
    __shared__ float  part[16][DHEAD];
    __shared__ float  red[DHEAD];
    __shared__ float  s_lr, s_max, s_sum;

    const int tid = threadIdx.x;
    if (tid < DHEAD) {
        s_ks[tid] = row[tid];
        s_vs[tid] = tanhf(row[DHEAD + tid]);
    }
    if (tid == 0) s_lr = 1.f / (1.f + expf(-row[2 * DHEAD]));
    __syncthreads();

    const int c4 = tid & 15;
    const int dg = tid >> 4;

    float p0 = 0.f, p1 = 0.f, p2 = 0.f, p3 = 0.f;
    #pragma unroll
    for (int i = 0; i < 4; i++) {
        int d = dg + 16 * i;
        float4 w = W4[d * 16 + c4];
        sW[d * 16 + c4] = w;
        float v = s_vs[d];
        p0 = fmaf(w.x, v, p0);
        p1 = fmaf(w.y, v, p1);
        p2 = fmaf(w.z, v, p2);
        p3 = fmaf(w.w, v, p3);
    }
    part[dg][4 * c4 + 0] = p0;
    part[dg][4 * c4 + 1] = p1;
    part[dg][4 * c4 + 2] = p2;
    part[dg][4 * c4 + 3] = p3;
    __syncthreads();

    if (tid < DHEAD) {
        float rm = 0.f;
        #pragma unroll
        for (int g = 0; g < 16; g++) rm += part[g][tid];
        red[tid] = s_ks[tid] - rm;
    }
    __syncthreads();
    if (tid == 0) {
        float mx = red[0];
        #pragma unroll
        for (int e = 1; e < DHEAD; e++) mx = fmaxf(mx, red[e]);
        s_max = mx;
    }
    __syncthreads();
    if (tid < DHEAD) red[tid] = expf(red[tid] - s_max);
    __syncthreads();
    if (tid == 0) {
        float s = 0.f;
        #pragma unroll
        for (int e = 0; e < DHEAD; e++) s += red[e];
        s_sum = s;
    }
    __syncthreads();
    if (tid < DHEAD) s_ks[tid] = red[tid] * (s_lr / s_sum);
    __syncthreads();

    #pragma unroll
    for (int i = 0; i < 4; i++) {
        int d = dg + 16 * i;
        float4 w = sW[d * 16 + c4];
        float v = s_vs[d];
        float4 o;
        o.x = fmaf(v, s_ks[4 * c4 + 0], w.x);
        o.y = fmaf(v, s_ks[4 * c4 + 1], w.y);
        o.z = fmaf(v, s_ks[4 * c4 + 2], w.z);
        o.w = fmaf(v, s_ks[4 * c4 + 3], w.w);
        O4[d * 16 + c4] = o;
    }
}

// ---------------- launch ----------------
extern "C" void kernel_launch(void* const* d_in, const int* in_sizes, int n_in,
                              void* d_out, int out_size)
{
    const float* x     = (const float*)d_in[0];
    const float* z     = (const float*)d_in[1];
    const float* W     = (const float*)d_in[2];
    const float* ip_w  = (const float*)d_in[3];
    const float* ip_b  = (const float*)d_in[4];
    const float* ln_g  = (const float*)d_in[5];
    const float* ln_b  = (const float*)d_in[6];
    const float* mg_w  = (const float*)d_in[7];
    const float* mg_b  = (const float*)d_in[8];
    const float* kvb_w = (const float*)d_in[9];
    const float* kvb_b = (const float*)d_in[10];
    float* out = (float*)d_out;

    void *p_hcat, *p_h2, *p_kvb;
    cudaGetSymbolAddress(&p_hcat, g_hcat);
    cudaGetSymbolAddress(&p_h2,   g_h2);
    cudaGetSymbolAddress(&p_kvb,  g_kvb);
    float* hcat = (float*)p_hcat;
    float* h2   = (float*)p_h2;
    float* kvb  = (float*)p_kvb;

    // 1) h = x @ ip_w + ip_b  -> hcat[:, :512]
    {
        dim3 grid(LATENT / GBN, BATCH / GBM);
        tf32_gemm<false><<<grid, 128>>>(BATCH, LATENT, INDIM, x, INDIM, ip_w, LATENT, ip_b, hcat, 1024);
    }
    // 2) LayerNorm in place + copy z into hcat[:, 512:]
    ln_concat_kernel<<<BATCH, 256>>>(z, ln_g, ln_b);
    // 3) h2 = hcat @ mg_w + mg_b
    {
        dim3 grid(LATENT / GBN, BATCH / GBM);
        tf32_gemm<false><<<grid, 128>>>(BATCH, LATENT, 1024, hcat, 1024, mg_w, LATENT, mg_b, h2, LATENT);
    }
    // 4) kvb = h2 @ kvb_w + kvb_b   (N=1032, needs bounds)
    {
        dim3 grid((KVBN + GBN - 1) / GBN, BATCH / GBM);
        tf32_gemm<true><<<grid, 128>>>(BATCH, KVBN, LATENT, h2, LATENT, kvb_w, KVBN, kvb_b, kvb, KVBN);
    }
    // 5) Oja update fused
    oja_final_kernel<<<BATCH * NHEAD, 256>>>(W, out);
}

// round 5
// speedup vs baseline: 1.7625x; 1.0605x over previous
#include <cuda_runtime.h>
#include <cuda_bf16.h>
#include <math.h>
#include <stdint.h>

// Problem constants
#define BATCH   4096
#define INDIM   512
#define LATENT  512
#define NHEAD   8
#define DHEAD   64
#define KVBN    1032            // H*(2D+1) = 8*129
#define LN_EPS  1e-5f

// ---------------- scratch (device globals; no runtime alloc allowed) ----------------
__device__ float g_hcat[BATCH * 1024];    // [h_ln | z] rounded to tf32 by LN  (ld = 1024)
__device__ float g_h2  [BATCH * LATENT];  // rounded to tf32 in GEMM2 epilogue
__device__ float g_kvb [BATCH * KVBN];
__device__ float g_xr  [BATCH * INDIM];   // x rounded to tf32
__device__ float g_ipw [INDIM * LATENT];
__device__ float g_mgw [1024 * LATENT];
__device__ float g_kvbw[LATENT * KVBN];

__device__ __forceinline__ float to_tf32(float x) {
    float y;
    asm("cvt.rna.tf32.f32 %0, %1;" : "=f"(y) : "f"(x));
    return y;
}
__device__ __forceinline__ uint32_t smem_u32(const void* p) {
    return (uint32_t)__cvta_generic_to_shared(p);
}
__device__ __forceinline__ void cp_async16(uint32_t dst, const void* src) {
    asm volatile("cp.async.cg.shared.global [%0], [%1], 16;\n" :: "r"(dst), "l"(src));
}
__device__ __forceinline__ void cp_commit() { asm volatile("cp.async.commit_group;\n"); }
__device__ __forceinline__ void cp_wait0()  { asm volatile("cp.async.wait_group 0;\n"); }
__device__ __forceinline__ void cp_wait1()  { asm volatile("cp.async.wait_group 1;\n"); }

// ---------------- elementwise tf32 rounding (pre-pass) ----------------
__global__ __launch_bounds__(256) void round_tf32_kernel(
    const float4* __restrict__ src, float4* __restrict__ dst, int n4)
{
    int i = blockIdx.x * 256 + threadIdx.x;
    int stride = gridDim.x * 256;
    for (; i < n4; i += stride) {
        float4 v = src[i];
        v.x = to_tf32(v.x); v.y = to_tf32(v.y);
        v.z = to_tf32(v.z); v.w = to_tf32(v.w);
        dst[i] = v;
    }
}

// ---------------- TF32 tensor-core GEMM: C = A(MxK) * B(KxN) + bias ----------------
// BM=128, BN=128, BK=16, 256 threads (8 warps: 2 along M x 4 along N), warp tile 64x32.
// Inputs MUST already be tf32-rounded. cp.async double-buffered.
// As [m][k] stride 20, Bs [k][n] stride 136 — both conflict-free for fragment LDS.
#define GBM 128
#define GBN 128
#define GBK 16
#define SA  20
#define SB  136

template<bool NB, bool ROUND_OUT>
__global__ __launch_bounds__(256, 2) void tf32_gemm(
    int M, int N, int K,
    const float* __restrict__ A, int lda,
    const float* __restrict__ B, int ldb,
    const float* __restrict__ bias,
    float* __restrict__ C, int ldc)
{
    __shared__ float As[2][GBM][SA];
    __shared__ float Bs[2][GBK][SB];

    const int tid  = threadIdx.x;
    const int wid  = tid >> 5;
    const int lane = tid & 31;
    const int grp  = lane >> 2;     // 0..7
    const int tig  = lane & 3;      // 0..3
    const int warp_m = (wid & 1) * 64;
    const int warp_n = (wid >> 1) * 32;
    const int block_row = blockIdx.y * GBM;
    const int block_col = blockIdx.x * GBN;

    float acc[4][4][4];
    #pragma unroll
    for (int a = 0; a < 4; a++)
        #pragma unroll
        for (int b = 0; b < 4; b++)
            #pragma unroll
            for (int c = 0; c < 4; c++) acc[a][b][c] = 0.f;

    const int KT = K / GBK;

    auto load_tiles = [&](int buf, int kt) {
        const int k0 = kt * GBK;
        // A: 128 rows x 4 float4; 512 float4 over 256 threads -> 2 each
        #pragma unroll
        for (int i = 0; i < 2; i++) {
            int idx = tid + 256 * i;
            int r = idx >> 2;
            int j = (idx & 3) * 4;
            cp_async16(smem_u32(&As[buf][r][j]), A + (size_t)(block_row + r) * lda + k0 + j);
        }
        // B: 16 k-rows x 32 float4; 512 float4 over 256 threads -> 2 each
        #pragma unroll
        for (int i = 0; i < 2; i++) {
            int idx = tid + 256 * i;
            int kk  = idx >> 5;
            int c4  = (idx & 31) * 4;
            if (!NB || (block_col + c4) < N) {
                cp_async16(smem_u32(&Bs[buf][kk][c4]),
                           B + (size_t)(k0 + kk) * ldb + block_col + c4);
            }
        }
    };

    load_tiles(0, 0);
    cp_commit();

    for (int kt = 0; kt < KT; kt++) {
        const int buf = kt & 1;
        if (kt + 1 < KT) {
            load_tiles(buf ^ 1, kt + 1);
            cp_commit();
            cp_wait1();
        } else {
            cp_wait0();
        }
        __syncthreads();

        #pragma unroll
        for (int ks = 0; ks < 2; ks++) {
            const int k = ks * 8;
            uint32_t af[4][4], bf[4][2];
            #pragma unroll
            for (int mt = 0; mt < 4; mt++) {
                int m0 = warp_m + mt * 16;
                af[mt][0] = __float_as_uint(As[buf][m0 + grp    ][k + tig]);
                af[mt][1] = __float_as_uint(As[buf][m0 + grp + 8][k + tig]);
                af[mt][2] = __float_as_uint(As[buf][m0 + grp    ][k + tig + 4]);
                af[mt][3] = __float_as_uint(As[buf][m0 + grp + 8][k + tig + 4]);
            }
            #pragma unroll
            for (int nt = 0; nt < 4; nt++) {
                int n0 = warp_n + nt * 8;
                bf[nt][0] = __float_as_uint(Bs[buf][k + tig    ][n0 + grp]);
                bf[nt][1] = __float_as_uint(Bs[buf][k + tig + 4][n0 + grp]);
            }
            #pragma unroll
            for (int mt = 0; mt < 4; mt++)
                #pragma unroll
                for (int nt = 0; nt < 4; nt++) {
                    asm volatile(
                        "mma.sync.aligned.m16n8k8.row.col.f32.tf32.tf32.f32 "
                        "{%0,%1,%2,%3}, {%4,%5,%6,%7}, {%8,%9}, {%0,%1,%2,%3};\n"
                        : "+f"(acc[mt][nt][0]), "+f"(acc[mt][nt][1]),
                          "+f"(acc[mt][nt][2]), "+f"(acc[mt][nt][3])
                        : "r"(af[mt][0]), "r"(af[mt][1]), "r"(af[mt][2]), "r"(af[mt][3]),
                          "r"(bf[nt][0]), "r"(bf[nt][1]));
                }
        }
        __syncthreads();
    }

    // Epilogue: bias add (+ optional tf32 rounding) + float2 stores
    #pragma unroll
    for (int mt = 0; mt < 4; mt++) {
        int r0 = block_row + warp_m + mt * 16 + grp;
        #pragma unroll
        for (int nt = 0; nt < 4; nt++) {
            int c = block_col + warp_n + nt * 8 + tig * 2;
            if (!NB || c < N) {
                float b0 = bias[c], b1 = bias[c + 1];
                float o00 = acc[mt][nt][0] + b0, o01 = acc[mt][nt][1] + b1;
                float o10 = acc[mt][nt][2] + b0, o11 = acc[mt][nt][3] + b1;
                if (ROUND_OUT) {
                    o00 = to_tf32(o00); o01 = to_tf32(o01);
                    o10 = to_tf32(o10); o11 = to_tf32(o11);
                }
                *(float2*)(C + (size_t)r0 * ldc + c)       = make_float2(o00, o01);
                *(float2*)(C + (size_t)(r0 + 8) * ldc + c) = make_float2(o10, o11);
            }
        }
    }
}

// ---------------- LayerNorm (512) in-place on g_hcat[:, :512] + copy z into [:, 512:1024] ----------------
// Outputs rounded to tf32 (they feed GEMM2 directly).
__global__ __launch_bounds__(256) void ln_concat_kernel(
    const float* __restrict__ z,
    const float* __restrict__ gamma,
    const float* __restrict__ beta)
{
    const int b = blockIdx.x;
    float* row = g_hcat + (size_t)b * 1024;
    const float* zr = z + (size_t)b * LATENT;
    const int tid = threadIdx.x;

    float v0 = row[tid];
    float v1 = row[tid + 256];

    __shared__ float red[256];
    red[tid] = v0 + v1;
    __syncthreads();
    #pragma unroll
    for (int s = 128; s > 0; s >>= 1) {
        if (tid < s) red[tid] += red[tid + s];
        __syncthreads();
    }
    const float mu = red[0] * (1.f / 512.f);
    __syncthreads();

    float d0 = v0 - mu, d1 = v1 - mu;
    red[tid] = d0 * d0 + d1 * d1;
    __syncthreads();
    #pragma unroll
    for (int s = 128; s > 0; s >>= 1) {
        if (tid < s) red[tid] += red[tid + s];
        __syncthreads();
    }
    const float var = red[0] * (1.f / 512.f);
    const float inv = rsqrtf(var + LN_EPS);

    row[tid]       = to_tf32(d0 * inv * gamma[tid]       + beta[tid]);
    row[tid + 256] = to_tf32(d1 * inv * gamma[tid + 256] + beta[tid + 256]);
    row[512 + tid]       = to_tf32(zr[tid]);
    row[512 + tid + 256] = to_tf32(zr[tid + 256]);
}

// ---------------- Oja update: one block per (b,h); W tile staged in SMEM (single HBM read) ----------------
__global__ __launch_bounds__(256) void oja_final_kernel(
    const float* __restrict__ W,
    float* __restrict__ out)
{
    const int bh = blockIdx.x;              // b*H + h
    const int b  = bh >> 3;
    const int h  = bh & 7;

    const float4* __restrict__ W4 = (const float4*)(W   + (size_t)bh * (DHEAD * DHEAD));
    float4* __restrict__       O4 = (float4*)      (out + (size_t)bh * (DHEAD * DHEAD));
    const float* __restrict__ row = g_kvb + (size_t)b * KVBN + h * (2 * DHEAD + 1);

    __shared__ float4 sW[DHEAD * DHEAD / 4];   // 16 KB
    __shared__ float  s_vs[DHEAD];
    __shared__ float  s_ks[DHEAD];
    __shared__ float  part[16][DHEAD];
    __shared__ float  red[DHEAD];
    __shared__ float  s_lr, s_max, s_sum;

    const int tid = threadIdx.x;
    if (tid < DHEAD) {
        s_ks[tid] = row[tid];
        s_vs[tid] = tanhf(row[DHEAD + tid]);
    }
    if (tid == 0) s_lr = 1.f / (1.f + expf(-row[2 * DHEAD]));
    __syncthreads();

    const int c4 = tid & 15;
    const int dg = tid >> 4;

    float p0 = 0.f, p1 = 0.f, p2 = 0.f, p3 = 0.f;
    #pragma unroll
    for (int i = 0; i < 4; i++) {
        int d = dg + 16 * i;
        float4 w = W4[d * 16 + c4];
        sW[d * 16 + c4] = w;
        float v = s_vs[d];
        p0 = fmaf(w.x, v, p0);
        p1 = fmaf(w.y, v, p1);
        p2 = fmaf(w.z, v, p2);
        p3 = fmaf(w.w, v, p3);
    }
    part[dg][4 * c4 + 0] = p0;
    part[dg][4 * c4 + 1] = p1;
    part[dg][4 * c4 + 2] = p2;
    part[dg][4 * c4 + 3] = p3;
    __syncthreads();

    if (tid < DHEAD) {
        float rm = 0.f;
        #pragma unroll
        for (int g = 0; g < 16; g++) rm += part[g][tid];
        red[tid] = s_ks[tid] - rm;
    }
    __syncthreads();
    if (tid < 32) {
        float a = red[tid], bb = red[tid + 32];
        float mx = fmaxf(a, bb);
        #pragma unroll
        for (int o = 16; o > 0; o >>= 1) mx = fmaxf(mx, __shfl_xor_sync(0xffffffffu, mx, o));
        if (tid == 0) s_max = mx;
    }
    __syncthreads();
    if (tid < DHEAD) red[tid] = expf(red[tid] - s_max);
    __syncthreads();
    if (tid < 32) {
        float s = red[tid] + red[tid + 32];
        #pragma unroll
        for (int o = 16; o > 0; o >>= 1) s += __shfl_xor_sync(0xffffffffu, s, o);
        if (tid == 0) s_sum = s;
    }
    __syncthreads();
    if (tid < DHEAD) s_ks[tid] = red[tid] * (s_lr / s_sum);
    __syncthreads();

    #pragma unroll
    for (int i = 0; i < 4; i++) {
        int d = dg + 16 * i;
        float4 w = sW[d * 16 + c4];
        float v = s_vs[d];
        float4 o;
        o.x = fmaf(v, s_ks[4 * c4 + 0], w.x);
        o.y = fmaf(v, s_ks[4 * c4 + 1], w.y);
        o.z = fmaf(v, s_ks[4 * c4 + 2], w.z);
        o.w = fmaf(v, s_ks[4 * c4 + 3], w.w);
        O4[d * 16 + c4] = o;
    }
}

// ---------------- launch ----------------
extern "C" void kernel_launch(void* const* d_in, const int* in_sizes, int n_in,
                              void* d_out, int out_size)
{
    const float* x     = (const float*)d_in[0];
    const float* z     = (const float*)d_in[1];
    const float* W     = (const float*)d_in[2];
    const float* ip_w  = (const float*)d_in[3];
    const float* ip_b  = (const float*)d_in[4];
    const float* ln_g  = (const float*)d_in[5];
    const float* ln_b  = (const float*)d_in[6];
    const float* mg_w  = (const float*)d_in[7];
    const float* mg_b  = (const float*)d_in[8];
    const float* kvb_w = (const float*)d_in[9];
    const float* kvb_b = (const float*)d_in[10];
    float* out = (float*)d_out;

    void *p_hcat, *p_h2, *p_kvb, *p_xr, *p_ipw, *p_mgw, *p_kvbw;
    cudaGetSymbolAddress(&p_hcat, g_hcat);
    cudaGetSymbolAddress(&p_h2,   g_h2);
    cudaGetSymbolAddress(&p_kvb,  g_kvb);
    cudaGetSymbolAddress(&p_xr,   g_xr);
    cudaGetSymbolAddress(&p_ipw,  g_ipw);
    cudaGetSymbolAddress(&p_mgw,  g_mgw);
    cudaGetSymbolAddress(&p_kvbw, g_kvbw);
    float* hcat = (float*)p_hcat;
    float* h2   = (float*)p_h2;
    float* kvb  = (float*)p_kvb;

    // 0) pre-round x and weights to tf32 (removes all cvt from GEMM inner loops)
    {
        int n4;
        n4 = BATCH * INDIM / 4;
        round_tf32_kernel<<<592, 256>>>((const float4*)x, (float4*)p_xr, n4);
        n4 = INDIM * LATENT / 4;
        round_tf32_kernel<<<256, 256>>>((const float4*)ip_w, (float4*)p_ipw, n4);
        n4 = 1024 * LATENT / 4;
        round_tf32_kernel<<<512, 256>>>((const float4*)mg_w, (float4*)p_mgw, n4);
        n4 = LATENT * KVBN / 4;
        round_tf32_kernel<<<516, 256>>>((const float4*)kvb_w, (float4*)p_kvbw, n4);
    }

    // 1) h = xr @ ipw + ip_b  -> hcat[:, :512]  (fp32 out; LN rounds)
    {
        dim3 grid(LATENT / GBN, BATCH / GBM);
        tf32_gemm<false, false><<<grid, 256>>>(BATCH, LATENT, INDIM,
            (const float*)p_xr, INDIM, (const float*)p_ipw, LATENT, ip_b, hcat, 1024);
    }
    // 2) LayerNorm in place (tf32-rounded out) + rounded z copy
    ln_concat_kernel<<<BATCH, 256>>>(z, ln_g, ln_b);
    // 3) h2 = hcat @ mgw + mg_b (tf32-rounded out)
    {
        dim3 grid(LATENT / GBN, BATCH / GBM);
        tf32_gemm<false, true><<<grid, 256>>>(BATCH, LATENT, 1024,
            hcat, 1024, (const float*)p_mgw, LATENT, mg_b, h2, LATENT);
    }
    // 4) kvb = h2 @ kvbw + kvb_b   (N=1032, bounds)
    {
        dim3 grid((KVBN + GBN - 1) / GBN, BATCH / GBM);
        tf32_gemm<true, false><<<grid, 256>>>(BATCH, KVBN, LATENT,
            h2, LATENT, (const float*)p_kvbw, KVBN, kvb_b, kvb, KVBN);
    }
    // 5) Oja update fused
    oja_final_kernel<<<BATCH * NHEAD, 256>>>(W, out);
}

// round 6
// speedup vs baseline: 2.1621x; 1.2267x over previous
#include <cuda_runtime.h>
#include <cuda_fp16.h>
#include <math.h>
#include <stdint.h>

// Problem constants
#define BATCH   4096
#define INDIM   512
#define LATENT  512
#define NHEAD   8
#define DHEAD   64
#define KVBN    1032            // H*(2D+1) = 8*129
#define LN_EPS  1e-5f

// ---------------- scratch (device globals; no runtime alloc allowed) ----------------
__device__ __half g_xh   [BATCH * INDIM];
__device__ __half g_ipwh [INDIM * LATENT];
__device__ __half g_mgwh [1024 * LATENT];
__device__ __half g_kvbwh[LATENT * KVBN];
__device__ float  g_h1   [BATCH * LATENT];   // GEMM1 out (fp32, pre-LN)
__device__ __half g_hcath[BATCH * 1024];     // [LN(h) | z] fp16
__device__ __half g_h2h  [BATCH * LATENT];   // GEMM2 out fp16
__device__ float  g_kvb  [BATCH * KVBN];     // GEMM3 out fp32

__device__ __forceinline__ uint32_t smem_u32(const void* p) {
    return (uint32_t)__cvta_generic_to_shared(p);
}
__device__ __forceinline__ void cp_async16(uint32_t dst, const void* src) {
    asm volatile("cp.async.cg.shared.global [%0], [%1], 16;\n" :: "r"(dst), "l"(src));
}
__device__ __forceinline__ void cp_commit() { asm volatile("cp.async.commit_group;\n"); }
__device__ __forceinline__ void cp_wait1()  { asm volatile("cp.async.wait_group 1;\n"); }

__device__ __forceinline__ void ldsm_x4(uint32_t& r0, uint32_t& r1, uint32_t& r2, uint32_t& r3, uint32_t addr) {
    asm volatile("ldmatrix.sync.aligned.m8n8.x4.shared.b16 {%0,%1,%2,%3}, [%4];"
                 : "=r"(r0), "=r"(r1), "=r"(r2), "=r"(r3) : "r"(addr));
}
__device__ __forceinline__ void ldsm_x4_t(uint32_t& r0, uint32_t& r1, uint32_t& r2, uint32_t& r3, uint32_t addr) {
    asm volatile("ldmatrix.sync.aligned.m8n8.x4.trans.shared.b16 {%0,%1,%2,%3}, [%4];"
                 : "=r"(r0), "=r"(r1), "=r"(r2), "=r"(r3) : "r"(addr));
}

// ---------------- fused f32 -> f16 conversion pre-pass (one launch) ----------------
__global__ __launch_bounds__(256) void cvt_half_kernel(
    const float2* __restrict__ s0, __half2* __restrict__ d0, int n0,
    const float2* __restrict__ s1, __half2* __restrict__ d1, int n1,
    const float2* __restrict__ s2, __half2* __restrict__ d2, int n2,
    const float2* __restrict__ s3, __half2* __restrict__ d3, int n3)
{
    const int t = blockIdx.x * 256 + threadIdx.x;
    const int stride = gridDim.x * 256;
    for (int i = t; i < n0; i += stride) d0[i] = __float22half2_rn(s0[i]);
    for (int i = t; i < n1; i += stride) d1[i] = __float22half2_rn(s1[i]);
    for (int i = t; i < n2; i += stride) d2[i] = __float22half2_rn(s2[i]);
    for (int i = t; i < n3; i += stride) d3[i] = __float22half2_rn(s3[i]);
}

// ---------------- fp16 tensor-core GEMM: C = A(MxK) * B(KxN) + bias ----------------
// BM=128, BN=128, BK=32, 256 threads (8 warps: 2 along M x 4 along N), warp tile 64x32.
// m16n8k16 f16 mma, f32 accumulate. 3-stage cp.async ring, ldmatrix fragment loads.
// As stride 40 halves, Bs stride 136 halves: both conflict-free for ldmatrix phases.
#define HGBM 128
#define HGBN 128
#define HGBK 32
#define SAH  40
#define SBH  136
#define NST  3

template<bool NB, typename OutT>
__global__ __launch_bounds__(256, 2) void h_gemm(
    int M, int N, int K,
    const __half* __restrict__ A, int lda,
    const __half* __restrict__ B, int ldb,
    const float* __restrict__ bias,
    OutT* __restrict__ C, int ldc)
{
    __shared__ __half As[NST][HGBM][SAH];
    __shared__ __half Bs[NST][HGBK][SBH];

    const int tid  = threadIdx.x;
    const int wid  = tid >> 5;
    const int lane = tid & 31;
    const int grp  = lane >> 2;
    const int tig  = lane & 3;
    const int warp_m = (wid & 1) * 64;
    const int warp_n = (wid >> 1) * 32;
    const int block_row = blockIdx.y * HGBM;
    const int block_col = blockIdx.x * HGBN;

    float acc[4][4][4];
    #pragma unroll
    for (int a = 0; a < 4; a++)
        #pragma unroll
        for (int b = 0; b < 4; b++)
            #pragma unroll
            for (int c = 0; c < 4; c++) acc[a][b][c] = 0.f;

    const int KT = K / HGBK;

    auto load_stage = [&](int s, int kt) {
        const int k0 = kt * HGBK;
        // A: 128 rows x 32 halves = 4 chunks/row, 512 chunks -> 2/thread
        #pragma unroll
        for (int i = 0; i < 2; i++) {
            int idx = tid + 256 * i;
            int r = idx >> 2;
            int j = (idx & 3) * 8;       // half offset in row
            cp_async16(smem_u32(&As[s][r][j]),
                       A + (size_t)(block_row + r) * lda + k0 + j);
        }
        // B: 32 k-rows x 128 halves = 16 chunks/row, 512 chunks -> 2/thread
        #pragma unroll
        for (int i = 0; i < 2; i++) {
            int idx = tid + 256 * i;
            int kk = idx >> 4;
            int c8 = (idx & 15) * 8;
            if (!NB || (block_col + c8) < N) {
                cp_async16(smem_u32(&Bs[s][kk][c8]),
                           B + (size_t)(k0 + kk) * ldb + block_col + c8);
            }
        }
    };

    load_stage(0, 0); cp_commit();
    load_stage(1, 1); cp_commit();

    // ldmatrix per-lane addressing (constant across iterations)
    const int a_row = warp_m + (lane & 15);
    const int a_k8  = (lane >> 4) << 3;          // 0 or 8 halves
    const int b_r16 = (lane & 15);
    const int b_n8  = (lane >> 4) << 3;

    for (int kt = 0; kt < KT; kt++) {
        cp_wait1();
        __syncthreads();
        if (kt + 2 < KT) load_stage((kt + 2) % NST, kt + 2);
        cp_commit();

        const int s = kt % NST;
        #pragma unroll
        for (int ks = 0; ks < 2; ks++) {
            const int k0 = ks * 16;
            uint32_t a[4][4];
            #pragma unroll
            for (int mt = 0; mt < 4; mt++) {
                uint32_t addr = smem_u32(&As[s][a_row + mt * 16][k0 + a_k8]);
                ldsm_x4(a[mt][0], a[mt][1], a[mt][2], a[mt][3], addr);
            }
            uint32_t b[2][4];
            #pragma unroll
            for (int bt = 0; bt < 2; bt++) {
                uint32_t addr = smem_u32(&Bs[s][k0 + b_r16][warp_n + bt * 16 + b_n8]);
                ldsm_x4_t(b[bt][0], b[bt][1], b[bt][2], b[bt][3], addr);
            }
            #pragma unroll
            for (int mt = 0; mt < 4; mt++)
                #pragma unroll
                for (int nt = 0; nt < 4; nt++) {
                    const int bt = nt >> 1;
                    const int hp = (nt & 1) * 2;
                    asm volatile(
                        "mma.sync.aligned.m16n8k16.row.col.f32.f16.f16.f32 "
                        "{%0,%1,%2,%3}, {%4,%5,%6,%7}, {%8,%9}, {%0,%1,%2,%3};\n"
                        : "+f"(acc[mt][nt][0]), "+f"(acc[mt][nt][1]),
                          "+f"(acc[mt][nt][2]), "+f"(acc[mt][nt][3])
                        : "r"(a[mt][0]), "r"(a[mt][1]), "r"(a[mt][2]), "r"(a[mt][3]),
                          "r"(b[bt][hp]), "r"(b[bt][hp + 1]));
                }
        }
    }

    // Epilogue: bias add + store (fp32 float2 or fp16 half2)
    #pragma unroll
    for (int mt = 0; mt < 4; mt++) {
        int r0 = block_row + warp_m + mt * 16 + grp;
        #pragma unroll
        for (int nt = 0; nt < 4; nt++) {
            int c = block_col + warp_n + nt * 8 + tig * 2;
            if (!NB || c < N) {
                float b0 = bias[c], b1 = bias[c + 1];
                float o00 = acc[mt][nt][0] + b0, o01 = acc[mt][nt][1] + b1;
                float o10 = acc[mt][nt][2] + b0, o11 = acc[mt][nt][3] + b1;
                if (sizeof(OutT) == 4) {
                    *(float2*)((float*)C + (size_t)r0 * ldc + c)       = make_float2(o00, o01);
                    *(float2*)((float*)C + (size_t)(r0 + 8) * ldc + c) = make_float2(o10, o11);
                } else {
                    *(__half2*)((__half*)C + (size_t)r0 * ldc + c)       = __floats2half2_rn(o00, o01);
                    *(__half2*)((__half*)C + (size_t)(r0 + 8) * ldc + c) = __floats2half2_rn(o10, o11);
                }
            }
        }
    }
}

// ---------------- LayerNorm (512) on g_h1 -> g_hcath[:, :512] (fp16) + z -> [:, 512:1024] ----------------
__global__ __launch_bounds__(256) void ln_concat_kernel(
    const float* __restrict__ z,
    const float* __restrict__ gamma,
    const float* __restrict__ beta)
{
    const int b = blockIdx.x;
    const float* row = g_h1 + (size_t)b * LATENT;
    const float* zr  = z + (size_t)b * LATENT;
    __half* oh = g_hcath + (size_t)b * 1024;
    const int tid = threadIdx.x;

    float v0 = row[tid];
    float v1 = row[tid + 256];

    __shared__ float red[256];
    red[tid] = v0 + v1;
    __syncthreads();
    #pragma unroll
    for (int s = 128; s > 0; s >>= 1) {
        if (tid < s) red[tid] += red[tid + s];
        __syncthreads();
    }
    const float mu = red[0] * (1.f / 512.f);
    __syncthreads();

    float d0 = v0 - mu, d1 = v1 - mu;
    red[tid] = d0 * d0 + d1 * d1;
    __syncthreads();
    #pragma unroll
    for (int s = 128; s > 0; s >>= 1) {
        if (tid < s) red[tid] += red[tid + s];
        __syncthreads();
    }
    const float var = red[0] * (1.f / 512.f);
    const float inv = rsqrtf(var + LN_EPS);

    oh[tid]       = __float2half(d0 * inv * gamma[tid]       + beta[tid]);
    oh[tid + 256] = __float2half(d1 * inv * gamma[tid + 256] + beta[tid + 256]);
    oh[512 + tid]       = __float2half(zr[tid]);
    oh[512 + tid + 256] = __float2half(zr[tid + 256]);
}

// ---------------- Oja update: one block per (b,h); W tile staged in SMEM (single HBM read) ----------------
__global__ __launch_bounds__(256) void oja_final_kernel(
    const float* __restrict__ W,
    float* __restrict__ out)
{
    const int bh = blockIdx.x;              // b*H + h
    const int b  = bh >> 3;
    const int h  = bh & 7;

    const float4* __restrict__ W4 = (const float4*)(W   + (size_t)bh * (DHEAD * DHEAD));
    float4* __restrict__       O4 = (float4*)      (out + (size_t)bh * (DHEAD * DHEAD));
    const float* __restrict__ row = g_kvb + (size_t)b * KVBN + h * (2 * DHEAD + 1);

    __shared__ float4 sW[DHEAD * DHEAD / 4];   // 16 KB
    __shared__ float  s_vs[DHEAD];
    __shared__ float  s_ks[DHEAD];
    __shared__ float  part[16][DHEAD];
    __shared__ float  red[DHEAD];
    __shared__ float  s_lr, s_max, s_sum;

    const int tid = threadIdx.x;
    if (tid < DHEAD) {
        s_ks[tid] = row[tid];
        s_vs[tid] = tanhf(row[DHEAD + tid]);
    }
    if (tid == 0) s_lr = 1.f / (1.f + expf(-row[2 * DHEAD]));
    __syncthreads();

    const int c4 = tid & 15;
    const int dg = tid >> 4;

    float p0 = 0.f, p1 = 0.f, p2 = 0.f, p3 = 0.f;
    #pragma unroll
    for (int i = 0; i < 4; i++) {
        int d = dg + 16 * i;
        float4 w = W4[d * 16 + c4];
        sW[d * 16 + c4] = w;
        float v = s_vs[d];
        p0 = fmaf(w.x, v, p0);
        p1 = fmaf(w.y, v, p1);
        p2 = fmaf(w.z, v, p2);
        p3 = fmaf(w.w, v, p3);
    }
    part[dg][4 * c4 + 0] = p0;
    part[dg][4 * c4 + 1] = p1;
    part[dg][4 * c4 + 2] = p2;
    part[dg][4 * c4 + 3] = p3;
    __syncthreads();

    if (tid < DHEAD) {
        float rm = 0.f;
        #pragma unroll
        for (int g = 0; g < 16; g++) rm += part[g][tid];
        red[tid] = s_ks[tid] - rm;
    }
    __syncthreads();
    if (tid < 32) {
        float a = red[tid], bb = red[tid + 32];
        float mx = fmaxf(a, bb);
        #pragma unroll
        for (int o = 16; o > 0; o >>= 1) mx = fmaxf(mx, __shfl_xor_sync(0xffffffffu, mx, o));
        if (tid == 0) s_max = mx;
    }
    __syncthreads();
    if (tid < DHEAD) red[tid] = expf(red[tid] - s_max);
    __syncthreads();
    if (tid < 32) {
        float s = red[tid] + red[tid + 32];
        #pragma unroll
        for (int o = 16; o > 0; o >>= 1) s += __shfl_xor_sync(0xffffffffu, s, o);
        if (tid == 0) s_sum = s;
    }
    __syncthreads();
    if (tid < DHEAD) s_ks[tid] = red[tid] * (s_lr / s_sum);
    __syncthreads();

    #pragma unroll
    for (int i = 0; i < 4; i++) {
        int d = dg + 16 * i;
        float4 w = sW[d * 16 + c4];
        float v = s_vs[d];
        float4 o;
        o.x = fmaf(v, s_ks[4 * c4 + 0], w.x);
        o.y = fmaf(v, s_ks[4 * c4 + 1], w.y);
        o.z = fmaf(v, s_ks[4 * c4 + 2], w.z);
        o.w = fmaf(v, s_ks[4 * c4 + 3], w.w);
        O4[d * 16 + c4] = o;
    }
}

// ---------------- launch ----------------
extern "C" void kernel_launch(void* const* d_in, const int* in_sizes, int n_in,
                              void* d_out, int out_size)
{
    const float* x     = (const float*)d_in[0];
    const float* z     = (const float*)d_in[1];
    const float* W     = (const float*)d_in[2];
    const float* ip_w  = (const float*)d_in[3];
    const float* ip_b  = (const float*)d_in[4];
    const float* ln_g  = (const float*)d_in[5];
    const float* ln_b  = (const float*)d_in[6];
    const float* mg_w  = (const float*)d_in[7];
    const float* mg_b  = (const float*)d_in[8];
    const float* kvb_w = (const float*)d_in[9];
    const float* kvb_b = (const float*)d_in[10];
    float* out = (float*)d_out;

    void *p_xh, *p_ipwh, *p_mgwh, *p_kvbwh, *p_h1, *p_hcath, *p_h2h, *p_kvb;
    cudaGetSymbolAddress(&p_xh,    g_xh);
    cudaGetSymbolAddress(&p_ipwh,  g_ipwh);
    cudaGetSymbolAddress(&p_mgwh,  g_mgwh);
    cudaGetSymbolAddress(&p_kvbwh, g_kvbwh);
    cudaGetSymbolAddress(&p_h1,    g_h1);
    cudaGetSymbolAddress(&p_hcath, g_hcath);
    cudaGetSymbolAddress(&p_h2h,   g_h2h);
    cudaGetSymbolAddress(&p_kvb,   g_kvb);

    // 0) one fused f32->f16 conversion pass for x + the three weight matrices
    cvt_half_kernel<<<1184, 256>>>(
        (const float2*)x,     (__half2*)p_xh,    BATCH * INDIM / 2,
        (const float2*)ip_w,  (__half2*)p_ipwh,  INDIM * LATENT / 2,
        (const float2*)mg_w,  (__half2*)p_mgwh,  1024 * LATENT / 2,
        (const float2*)kvb_w, (__half2*)p_kvbwh, LATENT * KVBN / 2);

    // 1) h1 = xh @ ipwh + ip_b  (fp32 out)
    {
        dim3 grid(LATENT / HGBN, BATCH / HGBM);
        h_gemm<false, float><<<grid, 256>>>(BATCH, LATENT, INDIM,
            (const __half*)p_xh, INDIM, (const __half*)p_ipwh, LATENT, ip_b,
            (float*)p_h1, LATENT);
    }
    // 2) LayerNorm -> hcath (fp16) + z concat
    ln_concat_kernel<<<BATCH, 256>>>(z, ln_g, ln_b);
    // 3) h2h = hcath @ mgwh + mg_b  (fp16 out)
    {
        dim3 grid(LATENT / HGBN, BATCH / HGBM);
        h_gemm<false, __half><<<grid, 256>>>(BATCH, LATENT, 1024,
            (const __half*)p_hcath, 1024, (const __half*)p_mgwh, LATENT, mg_b,
            (__half*)p_h2h, LATENT);
    }
    // 4) kvb = h2h @ kvbwh + kvb_b  (fp32 out, N=1032 bounds)
    {
        dim3 grid((KVBN + HGBN - 1) / HGBN, BATCH / HGBM);
        h_gemm<true, float><<<grid, 256>>>(BATCH, KVBN, LATENT,
            (const __half*)p_h2h, LATENT, (const __half*)p_kvbwh, KVBN, kvb_b,
            (float*)p_kvb, KVBN);
    }
    // 5) Oja update fused
    oja_final_kernel<<<BATCH * NHEAD, 256>>>(W, out);
}

// round 7
// speedup vs baseline: 2.1993x; 1.0172x over previous
#include <cuda_runtime.h>
#include <cuda_fp16.h>
#include <math.h>
#include <stdint.h>

// Problem constants
#define BATCH   4096
#define INDIM   512
#define LATENT  512
#define NHEAD   8
#define DHEAD   64
#define KVBN    1032            // H*(2D+1) = 8*129
#define LN_EPS  1e-5f

// ---------------- scratch (device globals; no runtime alloc allowed) ----------------
__device__ __half g_xh   [BATCH * INDIM];
__device__ __half g_ipwh [INDIM * LATENT];
__device__ __half g_mgwh [1024 * LATENT];
__device__ __half g_kvbwh[LATENT * KVBN];
__device__ float  g_h1   [BATCH * LATENT];   // GEMM1 out (fp32, pre-LN)
__device__ __half g_hcath[BATCH * 1024];     // [LN(h) | z] fp16
__device__ __half g_h2h  [BATCH * LATENT];   // GEMM2 out fp16
__device__ float  g_kvb  [BATCH * KVBN];     // GEMM3 out fp32

__device__ __forceinline__ uint32_t smem_u32(const void* p) {
    return (uint32_t)__cvta_generic_to_shared(p);
}
__device__ __forceinline__ void cp_async16(uint32_t dst, const void* src) {
    asm volatile("cp.async.cg.shared.global [%0], [%1], 16;\n" :: "r"(dst), "l"(src));
}
__device__ __forceinline__ void cp_commit() { asm volatile("cp.async.commit_group;\n"); }
__device__ __forceinline__ void cp_wait1()  { asm volatile("cp.async.wait_group 1;\n"); }

__device__ __forceinline__ void ldsm_x4(uint32_t& r0, uint32_t& r1, uint32_t& r2, uint32_t& r3, uint32_t addr) {
    asm volatile("ldmatrix.sync.aligned.m8n8.x4.shared.b16 {%0,%1,%2,%3}, [%4];"
                 : "=r"(r0), "=r"(r1), "=r"(r2), "=r"(r3) : "r"(addr));
}
__device__ __forceinline__ void ldsm_x4_t(uint32_t& r0, uint32_t& r1, uint32_t& r2, uint32_t& r3, uint32_t addr) {
    asm volatile("ldmatrix.sync.aligned.m8n8.x4.trans.shared.b16 {%0,%1,%2,%3}, [%4];"
                 : "=r"(r0), "=r"(r1), "=r"(r2), "=r"(r3) : "r"(addr));
}

// ---------------- fused f32 -> f16 conversion pre-pass (one launch) ----------------
__global__ __launch_bounds__(256) void cvt_half_kernel(
    const float2* __restrict__ s0, __half2* __restrict__ d0, int n0,
    const float2* __restrict__ s1, __half2* __restrict__ d1, int n1,
    const float2* __restrict__ s2, __half2* __restrict__ d2, int n2,
    const float2* __restrict__ s3, __half2* __restrict__ d3, int n3)
{
    const int t = blockIdx.x * 256 + threadIdx.x;
    const int stride = gridDim.x * 256;
    for (int i = t; i < n0; i += stride) d0[i] = __float22half2_rn(s0[i]);
    for (int i = t; i < n1; i += stride) d1[i] = __float22half2_rn(s1[i]);
    for (int i = t; i < n2; i += stride) d2[i] = __float22half2_rn(s2[i]);
    for (int i = t; i < n3; i += stride) d3[i] = __float22half2_rn(s3[i]);
}

// ---------------- fp16 tensor-core GEMM: C = A(MxK) * B(KxN) + bias ----------------
// BM=128, BN=64, BK=32, 128 threads (4 warps: 2 along M x 2 along N), warp tile 64x32.
// m16n8k16 f16 mma, f32 accumulate. 3-stage cp.async ring, ldmatrix fragment loads.
// As stride 40 halves, Bs stride 72 halves: both conflict-free for ldmatrix phases.
#define HGBM 128
#define HGBN 64
#define HGBK 32
#define SAH  40
#define SBH  72
#define NST  3

template<bool NB, typename OutT>
__global__ __launch_bounds__(128, 4) void h_gemm(
    int M, int N, int K,
    const __half* __restrict__ A, int lda,
    const __half* __restrict__ B, int ldb,
    const float* __restrict__ bias,
    OutT* __restrict__ C, int ldc)
{
    __shared__ __half As[NST][HGBM][SAH];
    __shared__ __half Bs[NST][HGBK][SBH];

    const int tid  = threadIdx.x;
    const int wid  = tid >> 5;
    const int lane = tid & 31;
    const int grp  = lane >> 2;
    const int tig  = lane & 3;
    const int warp_m = (wid & 1) * 64;
    const int warp_n = (wid >> 1) * 32;
    const int block_row = blockIdx.y * HGBM;
    const int block_col = blockIdx.x * HGBN;

    float acc[4][4][4];
    #pragma unroll
    for (int a = 0; a < 4; a++)
        #pragma unroll
        for (int b = 0; b < 4; b++)
            #pragma unroll
            for (int c = 0; c < 4; c++) acc[a][b][c] = 0.f;

    const int KT = K / HGBK;

    auto load_stage = [&](int s, int kt) {
        const int k0 = kt * HGBK;
        // A: 128 rows x 32 halves = 4 chunks/row = 512 chunks -> 4/thread
        #pragma unroll
        for (int i = 0; i < 4; i++) {
            int idx = tid + 128 * i;
            int r = idx >> 2;
            int j = (idx & 3) * 8;
            cp_async16(smem_u32(&As[s][r][j]),
                       A + (size_t)(block_row + r) * lda + k0 + j);
        }
        // B: 32 k-rows x 64 halves = 8 chunks/row = 256 chunks -> 2/thread
        #pragma unroll
        for (int i = 0; i < 2; i++) {
            int idx = tid + 128 * i;
            int kk = idx >> 3;
            int c8 = (idx & 7) * 8;
            if (!NB || (block_col + c8) < N) {
                cp_async16(smem_u32(&Bs[s][kk][c8]),
                           B + (size_t)(k0 + kk) * ldb + block_col + c8);
            }
        }
    };

    load_stage(0, 0); cp_commit();
    load_stage(1, 1); cp_commit();

    // ldmatrix per-lane addressing (constant across iterations)
    const int a_row = warp_m + (lane & 15);
    const int a_k8  = (lane >> 4) << 3;          // 0 or 8 halves
    const int b_r16 = (lane & 15);
    const int b_n8  = (lane >> 4) << 3;

    for (int kt = 0; kt < KT; kt++) {
        cp_wait1();
        __syncthreads();
        if (kt + 2 < KT) load_stage((kt + 2) % NST, kt + 2);
        cp_commit();

        const int s = kt % NST;
        #pragma unroll
        for (int ks = 0; ks < 2; ks++) {
            const int k0 = ks * 16;
            uint32_t a[4][4];
            #pragma unroll
            for (int mt = 0; mt < 4; mt++) {
                uint32_t addr = smem_u32(&As[s][a_row + mt * 16][k0 + a_k8]);
                ldsm_x4(a[mt][0], a[mt][1], a[mt][2], a[mt][3], addr);
            }
            uint32_t b[2][4];
            #pragma unroll
            for (int bt = 0; bt < 2; bt++) {
                uint32_t addr = smem_u32(&Bs[s][k0 + b_r16][warp_n + bt * 16 + b_n8]);
                ldsm_x4_t(b[bt][0], b[bt][1], b[bt][2], b[bt][3], addr);
            }
            #pragma unroll
            for (int mt = 0; mt < 4; mt++)
                #pragma unroll
                for (int nt = 0; nt < 4; nt++) {
                    const int bt = nt >> 1;
                    const int hp = (nt & 1) * 2;
                    asm volatile(
                        "mma.sync.aligned.m16n8k16.row.col.f32.f16.f16.f32 "
                        "{%0,%1,%2,%3}, {%4,%5,%6,%7}, {%8,%9}, {%0,%1,%2,%3};\n"
                        : "+f"(acc[mt][nt][0]), "+f"(acc[mt][nt][1]),
                          "+f"(acc[mt][nt][2]), "+f"(acc[mt][nt][3])
                        : "r"(a[mt][0]), "r"(a[mt][1]), "r"(a[mt][2]), "r"(a[mt][3]),
                          "r"(b[bt][hp]), "r"(b[bt][hp + 1]));
                }
        }
    }

    // Epilogue: bias add + store (fp32 float2 or fp16 half2)
    #pragma unroll
    for (int mt = 0; mt < 4; mt++) {
        int r0 = block_row + warp_m + mt * 16 + grp;
        #pragma unroll
        for (int nt = 0; nt < 4; nt++) {
            int c = block_col + warp_n + nt * 8 + tig * 2;
            if (!NB || c < N) {
                float b0 = bias[c], b1 = bias[c + 1];
                float o00 = acc[mt][nt][0] + b0, o01 = acc[mt][nt][1] + b1;
                float o10 = acc[mt][nt][2] + b0, o11 = acc[mt][nt][3] + b1;
                if (sizeof(OutT) == 4) {
                    *(float2*)((float*)C + (size_t)r0 * ldc + c)       = make_float2(o00, o01);
                    *(float2*)((float*)C + (size_t)(r0 + 8) * ldc + c) = make_float2(o10, o11);
                } else {
                    *(__half2*)((__half*)C + (size_t)r0 * ldc + c)       = __floats2half2_rn(o00, o01);
                    *(__half2*)((__half*)C + (size_t)(r0 + 8) * ldc + c) = __floats2half2_rn(o10, o11);
                }
            }
        }
    }
}

// ---------------- LayerNorm (512) on g_h1 -> g_hcath[:, :512] (fp16) + z -> [:, 512:1024] ----------------
__global__ __launch_bounds__(256) void ln_concat_kernel(
    const float* __restrict__ z,
    const float* __restrict__ gamma,
    const float* __restrict__ beta)
{
    const int b = blockIdx.x;
    const float* row = g_h1 + (size_t)b * LATENT;
    const float* zr  = z + (size_t)b * LATENT;
    __half* oh = g_hcath + (size_t)b * 1024;
    const int tid = threadIdx.x;

    float v0 = row[tid];
    float v1 = row[tid + 256];

    __shared__ float red[256];
    red[tid] = v0 + v1;
    __syncthreads();
    #pragma unroll
    for (int s = 128; s > 0; s >>= 1) {
        if (tid < s) red[tid] += red[tid + s];
        __syncthreads();
    }
    const float mu = red[0] * (1.f / 512.f);
    __syncthreads();

    float d0 = v0 - mu, d1 = v1 - mu;
    red[tid] = d0 * d0 + d1 * d1;
    __syncthreads();
    #pragma unroll
    for (int s = 128; s > 0; s >>= 1) {
        if (tid < s) red[tid] += red[tid + s];
        __syncthreads();
    }
    const float var = red[0] * (1.f / 512.f);
    const float inv = rsqrtf(var + LN_EPS);

    oh[tid]       = __float2half(d0 * inv * gamma[tid]       + beta[tid]);
    oh[tid + 256] = __float2half(d1 * inv * gamma[tid + 256] + beta[tid + 256]);
    oh[512 + tid]       = __float2half(zr[tid]);
    oh[512 + tid + 256] = __float2half(zr[tid + 256]);
}

// ---------------- Oja update: one block per (b,h); W kept in registers (single streaming HBM read) --------
__global__ __launch_bounds__(256) void oja_final_kernel(
    const float* __restrict__ W,
    float* __restrict__ out)
{
    const int bh = blockIdx.x;              // b*H + h
    const int b  = bh >> 3;
    const int h  = bh & 7;

    const float4* __restrict__ W4 = (const float4*)(W   + (size_t)bh * (DHEAD * DHEAD));
    float4* __restrict__       O4 = (float4*)      (out + (size_t)bh * (DHEAD * DHEAD));
    const float* __restrict__ row = g_kvb + (size_t)b * KVBN + h * (2 * DHEAD + 1);

    __shared__ float  s_vs[DHEAD];
    __shared__ float  s_ks[DHEAD];
    __shared__ float  part[16][DHEAD];
    __shared__ float  red[DHEAD];
    __shared__ float  s_lr, s_max, s_sum;

    const int tid = threadIdx.x;
    if (tid < DHEAD) {
        s_ks[tid] = row[tid];
        s_vs[tid] = tanhf(row[DHEAD + tid]);
    }
    if (tid == 0) s_lr = 1.f / (1.f + expf(-row[2 * DHEAD]));
    __syncthreads();

    const int c4 = tid & 15;
    const int dg = tid >> 4;

    // Stream W once into registers; accumulate ks_remove partials.
    float4 wreg[4];
    float p0 = 0.f, p1 = 0.f, p2 = 0.f, p3 = 0.f;
    #pragma unroll
    for (int i = 0; i < 4; i++) {
        int d = dg + 16 * i;
        float4 w = __ldcs(&W4[d * 16 + c4]);
        wreg[i] = w;
        float v = s_vs[d];
        p0 = fmaf(w.x, v, p0);
        p1 = fmaf(w.y, v, p1);
        p2 = fmaf(w.z, v, p2);
        p3 = fmaf(w.w, v, p3);
    }
    part[dg][4 * c4 + 0] = p0;
    part[dg][4 * c4 + 1] = p1;
    part[dg][4 * c4 + 2] = p2;
    part[dg][4 * c4 + 3] = p3;
    __syncthreads();

    if (tid < DHEAD) {
        float rm = 0.f;
        #pragma unroll
        for (int g = 0; g < 16; g++) rm += part[g][tid];
        red[tid] = s_ks[tid] - rm;
    }
    __syncthreads();
    if (tid < 32) {
        float mx = fmaxf(red[tid], red[tid + 32]);
        #pragma unroll
        for (int o = 16; o > 0; o >>= 1) mx = fmaxf(mx, __shfl_xor_sync(0xffffffffu, mx, o));
        if (tid == 0) s_max = mx;
    }
    __syncthreads();
    if (tid < DHEAD) red[tid] = expf(red[tid] - s_max);
    __syncthreads();
    if (tid < 32) {
        float s = red[tid] + red[tid + 32];
        #pragma unroll
        for (int o = 16; o > 0; o >>= 1) s += __shfl_xor_sync(0xffffffffu, s, o);
        if (tid == 0) s_sum = s;
    }
    __syncthreads();
    if (tid < DHEAD) s_ks[tid] = red[tid] * (s_lr / s_sum);
    __syncthreads();

    const float k0 = s_ks[4 * c4 + 0];
    const float k1 = s_ks[4 * c4 + 1];
    const float k2 = s_ks[4 * c4 + 2];
    const float k3 = s_ks[4 * c4 + 3];
    #pragma unroll
    for (int i = 0; i < 4; i++) {
        int d = dg + 16 * i;
        float v = s_vs[d];
        float4 w = wreg[i];
        float4 o;
        o.x = fmaf(v, k0, w.x);
        o.y = fmaf(v, k1, w.y);
        o.z = fmaf(v, k2, w.z);
        o.w = fmaf(v, k3, w.w);
        __stcs(&O4[d * 16 + c4], o);
    }
}

// ---------------- launch ----------------
extern "C" void kernel_launch(void* const* d_in, const int* in_sizes, int n_in,
                              void* d_out, int out_size)
{
    const float* x     = (const float*)d_in[0];
    const float* z     = (const float*)d_in[1];
    const float* W     = (const float*)d_in[2];
    const float* ip_w  = (const float*)d_in[3];
    const float* ip_b  = (const float*)d_in[4];
    const float* ln_g  = (const float*)d_in[5];
    const float* ln_b  = (const float*)d_in[6];
    const float* mg_w  = (const float*)d_in[7];
    const float* mg_b  = (const float*)d_in[8];
    const float* kvb_w = (const float*)d_in[9];
    const float* kvb_b = (const float*)d_in[10];
    float* out = (float*)d_out;

    void *p_xh, *p_ipwh, *p_mgwh, *p_kvbwh, *p_h1, *p_hcath, *p_h2h, *p_kvb;
    cudaGetSymbolAddress(&p_xh,    g_xh);
    cudaGetSymbolAddress(&p_ipwh,  g_ipwh);
    cudaGetSymbolAddress(&p_mgwh,  g_mgwh);
    cudaGetSymbolAddress(&p_kvbwh, g_kvbwh);
    cudaGetSymbolAddress(&p_h1,    g_h1);
    cudaGetSymbolAddress(&p_hcath, g_hcath);
    cudaGetSymbolAddress(&p_h2h,   g_h2h);
    cudaGetSymbolAddress(&p_kvb,   g_kvb);

    // 0) one fused f32->f16 conversion pass for x + the three weight matrices
    cvt_half_kernel<<<1184, 256>>>(
        (const float2*)x,     (__half2*)p_xh,    BATCH * INDIM / 2,
        (const float2*)ip_w,  (__half2*)p_ipwh,  INDIM * LATENT / 2,
        (const float2*)mg_w,  (__half2*)p_mgwh,  1024 * LATENT / 2,
        (const float2*)kvb_w, (__half2*)p_kvbwh, LATENT * KVBN / 2);

    // 1) h1 = xh @ ipwh + ip_b  (fp32 out)
    {
        dim3 grid(LATENT / HGBN, BATCH / HGBM);
        h_gemm<false, float><<<grid, 128>>>(BATCH, LATENT, INDIM,
            (const __half*)p_xh, INDIM, (const __half*)p_ipwh, LATENT, ip_b,
            (float*)p_h1, LATENT);
    }
    // 2) LayerNorm -> hcath (fp16) + z concat
    ln_concat_kernel<<<BATCH, 256>>>(z, ln_g, ln_b);
    // 3) h2h = hcath @ mgwh + mg_b  (fp16 out)
    {
        dim3 grid(LATENT / HGBN, BATCH / HGBM);
        h_gemm<false, __half><<<grid, 128>>>(BATCH, LATENT, 1024,
            (const __half*)p_hcath, 1024, (const __half*)p_mgwh, LATENT, mg_b,
            (__half*)p_h2h, LATENT);
    }
    // 4) kvb = h2h @ kvbwh + kvb_b  (fp32 out, N=1032 bounds)
    {
        dim3 grid((KVBN + HGBN - 1) / HGBN, BATCH / HGBM);
        h_gemm<true, float><<<grid, 128>>>(BATCH, KVBN, LATENT,
            (const __half*)p_h2h, LATENT, (const __half*)p_kvbwh, KVBN, kvb_b,
            (float*)p_kvb, KVBN);
    }
    // 5) Oja update fused
    oja_final_kernel<<<BATCH * NHEAD, 256>>>(W, out);
}